// round 4
// baseline (speedup 1.0000x reference)
#include <cuda_runtime.h>
#include <math.h>

#define Bb   2
#define Nn   1024
#define DIMM 1024
#define Hh   8
#define DHh  64
#define DIi  512
#define BN   (Bb*Nn)
#define TG   8
#define JB   8

static __device__ __constant__ float EPSf = 1.1920929e-07f;

// ---------------- scratch ----------------
__device__ float g_xa[BN*DIMM];
__device__ float g_qi[BN*DIMM];
__device__ float g_ki[BN*DIMM];
__device__ float g_vi[BN*DIMM];
__device__ float g_qp[BN*DIi];
__device__ float g_kp[BN*DIi];
__device__ float g_vp[BN*DIi];
__device__ float g_y [BN*DIi];
__device__ float g_ga[BN*24];

// ---------------- tf32 helpers ----------------
__device__ __forceinline__ unsigned f2tf(float f) {
    unsigned r; asm("cvt.rna.tf32.f32 %0, %1;" : "=r"(r) : "f"(f)); return r;
}
__device__ __forceinline__ void mma_tf32(float* c, const unsigned* a, const unsigned* b) {
    asm volatile(
        "mma.sync.aligned.m16n8k8.row.col.f32.tf32.tf32.f32 "
        "{%0,%1,%2,%3}, {%4,%5,%6,%7}, {%8,%9}, {%0,%1,%2,%3};"
        : "+f"(c[0]), "+f"(c[1]), "+f"(c[2]), "+f"(c[3])
        : "r"(a[0]), "r"(a[1]), "r"(a[2]), "r"(a[3]), "r"(b[0]), "r"(b[1]));
}

// ---------------- 1. RMSNorm ----------------
__global__ void k_rmsnorm(const float* __restrict__ x, const float* __restrict__ w) {
    int row = blockIdx.x;
    int tid = threadIdx.x;
    const float4* xr = (const float4*)(x + (size_t)row * DIMM);
    float4 xv = xr[tid];
    float ss = xv.x*xv.x + xv.y*xv.y + xv.z*xv.z + xv.w*xv.w;
    #pragma unroll
    for (int o = 16; o > 0; o >>= 1) ss += __shfl_xor_sync(0xffffffffu, ss, o);
    __shared__ float sred[8];
    if ((tid & 31) == 0) sred[tid >> 5] = ss;
    __syncthreads();
    float tot = 0.f;
    #pragma unroll
    for (int i = 0; i < 8; i++) tot += sred[i];
    float inv = rsqrtf(tot * (1.0f / DIMM) + EPSf);
    float4 wv = ((const float4*)w)[tid];
    float4 o;
    o.x = xv.x * inv * wv.x; o.y = xv.y * inv * wv.y;
    o.z = xv.z * inv * wv.z; o.w = xv.w * inv * wv.w;
    ((float4*)g_xa)[(size_t)row * (DIMM/4) + tid] = o;
}

// ---------------- 2. fused 3x depthwise conv ----------------
__global__ void k_conv(const float* __restrict__ cq, const float* __restrict__ ck,
                       const float* __restrict__ cv) {
    int row = blockIdx.x;
    int b = row / Nn, t = row - b * Nn;
    int d4 = threadIdx.x;
    int d  = d4 * 4;
    float xr[4][4];
    #pragma unroll
    for (int jj = 0; jj < 4; jj++) {
        int tt = t - 2 + jj;
        float4 v = make_float4(0.f, 0.f, 0.f, 0.f);
        if (tt >= 0 && tt < Nn)
            v = ((const float4*)g_xa)[((size_t)(b*Nn + tt)) * (DIMM/4) + d4];
        xr[jj][0] = v.x; xr[jj][1] = v.y; xr[jj][2] = v.z; xr[jj][3] = v.w;
    }
    const float* cws[3] = {cq, ck, cv};
    float* outs[3] = {g_qi, g_ki, g_vi};
    #pragma unroll
    for (int cI = 0; cI < 3; cI++) {
        float oo[4];
        #pragma unroll
        for (int e = 0; e < 4; e++) {
            float4 wv = ((const float4*)cws[cI])[d + e];
            oo[e] = xr[0][e]*wv.x + xr[1][e]*wv.y + xr[2][e]*wv.z + xr[3][e]*wv.w;
        }
        ((float4*)outs[cI])[(size_t)row * (DIMM/4) + d4] =
            make_float4(oo[0], oo[1], oo[2], oo[3]);
    }
}

// ---------------- 3. tf32 tensor-core GEMM: 128x256 block, 64x64 warp -----
// A-frags and B-frags stored permuted in smem so each fragment load is one
// vector LDS. mma.m16n8k8 tf32, fp32 accumulate.
__device__ __forceinline__ void gemm_tc_body(const float* __restrict__ A,
                                             const float* __restrict__ Bm,
                                             float* __restrict__ C,
                                             int Nc, int Kc) {
    __shared__ unsigned As[2*8*128];    // [kc][mtile][lane*4+frag]
    __shared__ unsigned Bs[2*32*64];    // [kc][ntile][lane*2+frag]
    int tid = threadIdx.x;
    int lane = tid & 31, wid = tid >> 5;
    int wr = wid >> 2, wc = wid & 3;
    int gid = lane >> 2, tig = lane & 3;
    int row0 = blockIdx.y * 128, col0 = blockIdx.x * 256;

    float acc[4][8][4];
    #pragma unroll
    for (int i = 0; i < 4; i++)
        #pragma unroll
        for (int j = 0; j < 8; j++)
            #pragma unroll
            for (int q = 0; q < 4; q++) acc[i][j][q] = 0.f;

    // global-load thread mappings (k-invariant)
    int am[2], akq[2];
    #pragma unroll
    for (int p = 0; p < 2; p++) {
        int idx = tid * 2 + p;
        am[p] = idx >> 2; akq[p] = (idx & 3) * 4;
    }
    int bkr[4], bn4[4];
    #pragma unroll
    for (int p = 0; p < 4; p++) {
        int idx = tid + p * 256;
        bkr[p] = idx >> 6; bn4[p] = (idx & 63) * 4;
    }

    float4 ra[2], rb[4];
    #pragma unroll
    for (int p = 0; p < 2; p++)
        ra[p] = *(const float4*)(A + (size_t)(row0 + am[p]) * Kc + akq[p]);
    #pragma unroll
    for (int p = 0; p < 4; p++)
        rb[p] = *(const float4*)(Bm + (size_t)bkr[p] * Nc + col0 + bn4[p]);

    for (int k0 = 0; k0 < Kc; k0 += 16) {
        // store current tiles (permuted, cvt to tf32)
        #pragma unroll
        for (int p = 0; p < 2; p++) {
            float v[4] = {ra[p].x, ra[p].y, ra[p].z, ra[p].w};
            int m = am[p], ri = m & 15, mt = m >> 4;
            #pragma unroll
            for (int e = 0; e < 4; e++) {
                int k = akq[p] + e;
                int kc = k >> 3, ci = k & 7;
                int l = ((ri & 7) << 2) | (ci & 3);
                int f = ((ci >> 2) << 1) | (ri >> 3);
                As[kc*1024 + mt*128 + l*4 + f] = f2tf(v[e]);
            }
        }
        #pragma unroll
        for (int p = 0; p < 4; p++) {
            float v[4] = {rb[p].x, rb[p].y, rb[p].z, rb[p].w};
            int kr = bkr[p], kc = kr >> 3, ri = kr & 7;
            #pragma unroll
            for (int e = 0; e < 4; e++) {
                int n = bn4[p] + e;
                int ni = n & 7, nt = n >> 3;
                int l = (ni << 2) | (ri & 3);
                int f = ri >> 2;
                Bs[kc*2048 + nt*64 + l*2 + f] = f2tf(v[e]);
            }
        }
        __syncthreads();
        if (k0 + 16 < Kc) {
            int kn = k0 + 16;
            #pragma unroll
            for (int p = 0; p < 2; p++)
                ra[p] = *(const float4*)(A + (size_t)(row0 + am[p]) * Kc + kn + akq[p]);
            #pragma unroll
            for (int p = 0; p < 4; p++)
                rb[p] = *(const float4*)(Bm + (size_t)(kn + bkr[p]) * Nc + col0 + bn4[p]);
        }
        #pragma unroll
        for (int kc = 0; kc < 2; kc++) {
            uint4 af[4];
            #pragma unroll
            for (int mi = 0; mi < 4; mi++) {
                int mt = wr * 4 + mi;
                af[mi] = *(const uint4*)&As[kc*1024 + mt*128 + lane*4];
            }
            #pragma unroll
            for (int ni = 0; ni < 8; ni++) {
                int nt = wc * 8 + ni;
                uint2 bf = *(const uint2*)&Bs[kc*2048 + nt*64 + lane*2];
                unsigned bb[2] = {bf.x, bf.y};
                #pragma unroll
                for (int mi = 0; mi < 4; mi++) {
                    unsigned aa[4] = {af[mi].x, af[mi].y, af[mi].z, af[mi].w};
                    mma_tf32(acc[mi][ni], aa, bb);
                }
            }
        }
        __syncthreads();
    }
    // epilogue
    #pragma unroll
    for (int mi = 0; mi < 4; mi++) {
        #pragma unroll
        for (int ni = 0; ni < 8; ni++) {
            int row = row0 + (wr*4 + mi)*16 + gid;
            int col = col0 + (wc*8 + ni)*8 + tig*2;
            *(float2*)(C + (size_t)row * Nc + col) =
                make_float2(acc[mi][ni][0], acc[mi][ni][1]);
            *(float2*)(C + (size_t)(row+8) * Nc + col) =
                make_float2(acc[mi][ni][2], acc[mi][ni][3]);
        }
    }
}

__global__ __launch_bounds__(256, 1)
void k_gemm3(const float* __restrict__ A0, const float* __restrict__ A1,
             const float* __restrict__ A2, const float* __restrict__ B0,
             const float* __restrict__ B1, const float* __restrict__ B2,
             float* __restrict__ C0, float* __restrict__ C1,
             float* __restrict__ C2, int Nc, int Kc) {
    const float* A = (blockIdx.z == 0) ? A0 : ((blockIdx.z == 1) ? A1 : A2);
    const float* Bm = (blockIdx.z == 0) ? B0 : ((blockIdx.z == 1) ? B1 : B2);
    float* C = (blockIdx.z == 0) ? C0 : ((blockIdx.z == 1) ? C1 : C2);
    gemm_tc_body(A, Bm, C, Nc, Kc);
}

__global__ __launch_bounds__(256, 1)
void k_gemm1(const float* __restrict__ A, const float* __restrict__ Bm,
             float* __restrict__ C, int Nc, int Kc) {
    gemm_tc_body(A, Bm, C, Nc, Kc);
}

// ---------------- 4. gate projections, split-K, 64-row tiles --------------
__global__ void k_gates2(const float* __restrict__ lw, const float* __restrict__ dw,
                         const float* __restrict__ mw) {
    __shared__ float As[64][20];
    __shared__ float Ws[16][24];
    int tid = threadIdx.x;
    int hh = tid & 7, ty = tid >> 3;          // ty 0..31 -> 2 rows each
    int row0 = blockIdx.x * 64;
    int kbase = blockIdx.y * 128;
    float acc[2][3] = {};
    for (int k0 = kbase; k0 < kbase + 128; k0 += 16) {
        {
            int m = tid >> 2, kq = (tid & 3) * 4;
            float4 v = *(const float4*)(g_xa + (size_t)(row0+m)*DIMM + k0 + kq);
            As[m][kq+0]=v.x; As[m][kq+1]=v.y; As[m][kq+2]=v.z; As[m][kq+3]=v.w;
        }
        if (tid < 128) {
            int kk = tid >> 3, h2 = tid & 7;
            Ws[kk][h2]    = lw[(k0+kk)*Hh + h2];
            Ws[kk][8+h2]  = dw[(k0+kk)*Hh + h2];
            Ws[kk][16+h2] = mw[(k0+kk)*Hh + h2];
        }
        __syncthreads();
        #pragma unroll
        for (int kk = 0; kk < 16; kk++) {
            float a0 = As[ty*2][kk], a1 = As[ty*2+1][kk];
            float w0 = Ws[kk][hh], w1 = Ws[kk][8+hh], w2 = Ws[kk][16+hh];
            acc[0][0] += a0*w0; acc[0][1] += a0*w1; acc[0][2] += a0*w2;
            acc[1][0] += a1*w0; acc[1][1] += a1*w1; acc[1][2] += a1*w2;
        }
        __syncthreads();
    }
    #pragma unroll
    for (int i = 0; i < 2; i++) {
        int row = row0 + ty*2 + i;
        atomicAdd(&g_ga[row*24 + hh],      acc[i][0]);
        atomicAdd(&g_ga[row*24 + 8 + hh],  acc[i][1]);
        atomicAdd(&g_ga[row*24 + 16 + hh], acc[i][2]);
    }
}

// ---------------- 5. per-head RMSNorm of q, k ----------------
__global__ void k_mhnorm(const float* __restrict__ gq, const float* __restrict__ gk) {
    int row = blockIdx.x;
    int h = threadIdx.x >> 5, l = threadIdx.x & 31;
    size_t off = (size_t)row * DIi + h * DHh;
    {
        float a0 = g_qp[off + l], a1 = g_qp[off + l + 32];
        float ss = a0*a0 + a1*a1;
        #pragma unroll
        for (int o = 16; o > 0; o >>= 1) ss += __shfl_xor_sync(0xffffffffu, ss, o);
        float inv = 1.f / fmaxf(sqrtf(ss) * 0.125f, 1e-8f);
        g_qp[off + l]      = a0 * inv * gq[h*DHh + l];
        g_qp[off + l + 32] = a1 * inv * gq[h*DHh + l + 32];
    }
    {
        float a0 = g_kp[off + l], a1 = g_kp[off + l + 32];
        float ss = a0*a0 + a1*a1;
        #pragma unroll
        for (int o = 16; o > 0; o >>= 1) ss += __shfl_xor_sync(0xffffffffu, ss, o);
        float inv = 1.f / fmaxf(sqrtf(ss) * 0.125f, 1e-8f);
        g_kp[off + l]      = a0 * inv * gk[h*DHh + l];
        g_kp[off + l + 32] = a1 * inv * gk[h*DHh + l + 32];
    }
}

// ---------------- 6. scan: 8 col-blocks per (b,h), 8-step groups ----------
__global__ void k_scan(const float* __restrict__ lb, const float* __restrict__ db,
                       const float* __restrict__ mb) {
    int bh = blockIdx.x >> 3, jb = blockIdx.x & 7;
    int b = bh >> 3, h = bh & 7;
    int j0g = jb * JB;
    int tid = threadIdx.x;           // 256
    int r = tid >> 2, c = tid & 3;   // row, col-pair group (2 cols each)
    __shared__ float sq[2][TG][JB], sk[2][TG][JB], sv[2][TG][64], sg[2][TG][4];
    float Z0=0.f, Z1=0.f, S0=0.f, S1=0.f;
    const size_t base = (size_t)b * Nn * DIi + h * DHh;

    int vstep = tid >> 6, vrow = tid & 63;
    bool qrole = (tid < 64), krole = (tid >= 64 && tid < 128);
    bool grole = (tid >= 128 && tid < 152);
    int qkstep = (tid & 63) >> 3, qkj = tid & 7;
    int gidx = tid - 128;
    int gstep = gidx / 3, ggi = gidx - gstep * 3;
    float gbias = 0.f;
    if (grole) {
        const float* bsrc = (ggi == 0) ? lb : ((ggi == 1) ? db : mb);
        gbias = bsrc[h];
    }

    float pv0, pv1, pq = 0.f, pk = 0.f, pg = 0.f;
    pv0 = g_vp[base + (size_t)vstep * DIi + vrow];
    pv1 = g_vp[base + (size_t)(vstep+4) * DIi + vrow];
    if (qrole) pq = g_qp[base + (size_t)qkstep * DIi + j0g + qkj];
    if (krole) pk = g_kp[base + (size_t)qkstep * DIi + j0g + qkj];
    if (grole) {
        float raw = g_ga[(size_t)(b*Nn + gstep)*24 + ggi*8 + h] + gbias;
        pg = 1.f / (1.f + __expf(-raw));
    }
    sv[0][vstep][vrow] = pv0;
    sv[0][vstep+4][vrow] = pv1;
    if (qrole) sq[0][qkstep][qkj] = pq;
    if (krole) sk[0][qkstep][qkj] = pk;
    if (grole) sg[0][gstep][ggi] = pg;
    __syncthreads();

    int cur = 0;
    for (int g0 = 0; g0 < Nn / TG; g0++) {
        int t0 = g0 * TG;
        bool hasnext = (g0 + 1 < Nn / TG);
        if (hasnext) {
            int tn = t0 + TG;
            pv0 = g_vp[base + (size_t)(tn+vstep) * DIi + vrow];
            pv1 = g_vp[base + (size_t)(tn+vstep+4) * DIi + vrow];
            if (qrole) pq = g_qp[base + (size_t)(tn+qkstep) * DIi + j0g + qkj];
            if (krole) pk = g_kp[base + (size_t)(tn+qkstep) * DIi + j0g + qkj];
            if (grole) {
                float raw = g_ga[(size_t)(b*Nn + tn + gstep)*24 + ggi*8 + h] + gbias;
                pg = 1.f / (1.f + __expf(-raw));
            }
        }
        #pragma unroll
        for (int s = 0; s < TG; s++) {
            float q0 = sq[cur][s][c*2], q1 = sq[cur][s][c*2+1];
            float p = S0*q0 + S1*q1;
            p += __shfl_xor_sync(0xffffffffu, p, 1);
            p += __shfl_xor_sync(0xffffffffu, p, 2);
            if (c == 0) atomicAdd(&g_y[base + (size_t)(t0+s)*DIi + r], p);
            float vr  = sv[cur][s][r];
            float k0v = sk[cur][s][c*2], k1v = sk[cur][s][c*2+1];
            float lrt = sg[cur][s][0], det = sg[cur][s][1], mot = sg[cur][s][2];
            Z0 = mot*Z0 - vr*k0v;  S0 = det*S0 - lrt*Z0;
            Z1 = mot*Z1 - vr*k1v;  S1 = det*S1 - lrt*Z1;
        }
        __syncthreads();
        if (hasnext) {
            int nxt = cur ^ 1;
            sv[nxt][vstep][vrow] = pv0;
            sv[nxt][vstep+4][vrow] = pv1;
            if (qrole) sq[nxt][qkstep][qkj] = pq;
            if (krole) sk[nxt][qkstep][qkj] = pk;
            if (grole) sg[nxt][gstep][ggi] = pg;
        }
        __syncthreads();
        cur ^= 1;
    }
}

// ---------------- launch ----------------
extern "C" void kernel_launch(void* const* d_in, const int* in_sizes, int n_in,
                              void* d_out, int out_size) {
    const float* x      = (const float*)d_in[0];
    const float* w_rms  = (const float*)d_in[1];
    const float* wq     = (const float*)d_in[2];
    const float* wk     = (const float*)d_in[3];
    const float* wv     = (const float*)d_in[4];
    const float* wo     = (const float*)d_in[5];
    const float* conv_q = (const float*)d_in[6];
    const float* conv_k = (const float*)d_in[7];
    const float* conv_v = (const float*)d_in[8];
    const float* gamma_q= (const float*)d_in[9];
    const float* gamma_k= (const float*)d_in[10];
    const float* lr_w   = (const float*)d_in[11];
    const float* lr_b   = (const float*)d_in[12];
    const float* decay_w= (const float*)d_in[13];
    const float* decay_b= (const float*)d_in[14];
    const float* mom_w  = (const float*)d_in[15];
    const float* mom_b  = (const float*)d_in[16];
    float* out = (float*)d_out;

    float *p_qi, *p_ki, *p_vi, *p_qp, *p_kp, *p_vp, *p_y, *p_ga;
    cudaGetSymbolAddress((void**)&p_qi, g_qi);
    cudaGetSymbolAddress((void**)&p_ki, g_ki);
    cudaGetSymbolAddress((void**)&p_vi, g_vi);
    cudaGetSymbolAddress((void**)&p_qp, g_qp);
    cudaGetSymbolAddress((void**)&p_kp, g_kp);
    cudaGetSymbolAddress((void**)&p_vp, g_vp);
    cudaGetSymbolAddress((void**)&p_y,  g_y);
    cudaGetSymbolAddress((void**)&p_ga, g_ga);

    cudaMemsetAsync(p_ga, 0, (size_t)BN * 24 * sizeof(float));
    cudaMemsetAsync(p_y,  0, (size_t)BN * DIi * sizeof(float));

    k_rmsnorm<<<BN, 256>>>(x, w_rms);
    k_conv<<<BN, 256>>>(conv_q, conv_k, conv_v);
    dim3 gqkv(DIi/256, BN/128, 3);
    k_gemm3<<<gqkv, 256>>>(p_qi, p_ki, p_vi, wq, wk, wv, p_qp, p_kp, p_vp, DIi, DIMM);
    dim3 ggate(BN/64, 8);
    k_gates2<<<ggate, 256>>>(lr_w, decay_w, mom_w);
    k_mhnorm<<<BN, 256>>>(gamma_q, gamma_k);
    k_scan<<<Bb*Hh*8, 256>>>(lr_b, decay_b, mom_b);
    dim3 gout(DIMM/256, BN/128);
    k_gemm1<<<gout, 256>>>(p_y, wo, out, DIMM, DIi);
}

// round 5
// speedup vs baseline: 1.3994x; 1.3994x over previous
#include <cuda_runtime.h>
#include <math.h>

#define Bb   2
#define Nn   1024
#define DIMM 1024
#define Hh   8
#define DHh  64
#define DIi  512
#define BN   (Bb*Nn)
#define TG   8
#define JB   8

static __device__ __constant__ float EPSf = 1.1920929e-07f;

// ---------------- scratch ----------------
__device__ float g_xa[BN*DIMM];
__device__ float g_qp[BN*DIi];
__device__ float g_kp[BN*DIi];
__device__ float g_vp[BN*DIi];
__device__ float g_y [BN*DIi];
__device__ float g_ga[BN*24];

// ---------------- tf32 helpers ----------------
__device__ __forceinline__ unsigned f2tf(float f) {
    unsigned r; asm("cvt.rna.tf32.f32 %0, %1;" : "=r"(r) : "f"(f)); return r;
}
__device__ __forceinline__ uint4 tf4(float4 v) {
    return make_uint4(f2tf(v.x), f2tf(v.y), f2tf(v.z), f2tf(v.w));
}
__device__ __forceinline__ void mma_tf32(float* c, const unsigned* a, const unsigned* b) {
    asm volatile(
        "mma.sync.aligned.m16n8k8.row.col.f32.tf32.tf32.f32 "
        "{%0,%1,%2,%3}, {%4,%5,%6,%7}, {%8,%9}, {%0,%1,%2,%3};"
        : "+f"(c[0]), "+f"(c[1]), "+f"(c[2]), "+f"(c[3])
        : "r"(a[0]), "r"(a[1]), "r"(a[2]), "r"(a[3]), "r"(b[0]), "r"(b[1]));
}

// ---------------- 1. RMSNorm ----------------
__global__ void k_rmsnorm(const float* __restrict__ x, const float* __restrict__ w) {
    int row = blockIdx.x;
    int tid = threadIdx.x;
    const float4* xr = (const float4*)(x + (size_t)row * DIMM);
    float4 xv = xr[tid];
    float ss = xv.x*xv.x + xv.y*xv.y + xv.z*xv.z + xv.w*xv.w;
    #pragma unroll
    for (int o = 16; o > 0; o >>= 1) ss += __shfl_xor_sync(0xffffffffu, ss, o);
    __shared__ float sred[8];
    if ((tid & 31) == 0) sred[tid >> 5] = ss;
    __syncthreads();
    float tot = 0.f;
    #pragma unroll
    for (int i = 0; i < 8; i++) tot += sred[i];
    float inv = rsqrtf(tot * (1.0f / DIMM) + EPSf);
    float4 wv = ((const float4*)w)[tid];
    float4 o;
    o.x = xv.x * inv * wv.x; o.y = xv.y * inv * wv.y;
    o.z = xv.z * inv * wv.z; o.w = xv.w * inv * wv.w;
    ((float4*)g_xa)[(size_t)row * (DIMM/4) + tid] = o;
}

// ---------------- 2. tf32 GEMM core: 128x256 block, 64x64 warp ------------
// A smem: [slab=k/4][m][4], slab stride 520 words (130x16B) -> conflict-free
// STS.128 and LDS.32. B smem: [ntile][k][8] -> addr16 = nt*32+lane.
// FC: fuse depthwise conv (K=4, pad 2) into the A global->smem stage.
template<bool FC>
__device__ __forceinline__ void gemm_tc(const float* __restrict__ A,
                                        const float* __restrict__ Bm,
                                        float* __restrict__ C,
                                        int Nc, int Kc,
                                        const float* __restrict__ cw) {
    __shared__ unsigned As[4*520];
    __shared__ unsigned Bs[32*128];
    int tid = threadIdx.x;
    int lane = tid & 31, wid = tid >> 5;
    int wr = wid >> 2, wc = wid & 3;
    int gid = lane >> 2, tig = lane & 3;
    int row0 = blockIdx.y * 128, col0 = blockIdx.x * 256;

    // A-load role: 2 threads per row
    int ar = tid >> 1;                 // row in tile 0..127
    int kqb = (tid & 1) * 2;           // + p -> k-quad 0..3
    // B-load role
    int bk = lane >> 1, bq = lane & 1; // k-row in tile, n-quad parity

    int m = row0 + ar;
    int tloc = 0, b0 = 0;
    if (FC) { b0 = m & ~(Nn - 1); tloc = m - b0; }

    float acc[4][8][4];
    #pragma unroll
    for (int i = 0; i < 4; i++)
        #pragma unroll
        for (int j = 0; j < 8; j++)
            #pragma unroll
            for (int q = 0; q < 4; q++) acc[i][j][q] = 0.f;

    float4 ra[2], rb[4];
    const float4* A4 = (const float4*)A;
    const float4* B4 = (const float4*)Bm;
    const float4* XA4 = (const float4*)g_xa;
    const float4* CW4 = (const float4*)cw;

    // ---- prefetch k-tile kn ----
    #define PREFETCH(kn)                                                        \
    {                                                                           \
        _Pragma("unroll")                                                       \
        for (int p = 0; p < 2; p++) {                                           \
            int kq = kqb + p;                                                   \
            if (!FC) {                                                          \
                ra[p] = A4[(size_t)m * (Kc >> 2) + ((kn) >> 2) + kq];           \
            } else {                                                            \
                int kb = (kn) + kq * 4;                                         \
                float we[4][4];                                                 \
                _Pragma("unroll")                                               \
                for (int e = 0; e < 4; e++) *(float4*)we[e] = CW4[kb + e];      \
                float4 r = make_float4(0.f, 0.f, 0.f, 0.f);                     \
                _Pragma("unroll")                                               \
                for (int j = 0; j < 4; j++) {                                   \
                    int tl = tloc + j - 2;                                      \
                    if ((unsigned)tl < (unsigned)Nn) {                          \
                        float4 xv = XA4[(size_t)(b0 + tl) * (DIMM >> 2) + (kb >> 2)]; \
                        r.x += xv.x * we[0][j]; r.y += xv.y * we[1][j];         \
                        r.z += xv.z * we[2][j]; r.w += xv.w * we[3][j];         \
                    }                                                           \
                }                                                               \
                ra[p] = r;                                                      \
            }                                                                   \
        }                                                                       \
        _Pragma("unroll")                                                       \
        for (int p = 0; p < 4; p++) {                                           \
            int nt = wid + p * 8;                                               \
            rb[p] = B4[(size_t)((kn) + bk) * (Nc >> 2) + (col0 >> 2) + nt * 2 + bq]; \
        }                                                                       \
    }

    PREFETCH(0)

    for (int k0 = 0; k0 < Kc; k0 += 16) {
        // store to smem (all STS.128, conflict-free phases)
        #pragma unroll
        for (int p = 0; p < 2; p++) {
            int slab = kqb + p;
            *(uint4*)&As[slab*520 + ar*4] = tf4(ra[p]);
        }
        #pragma unroll
        for (int p = 0; p < 4; p++) {
            int nt = wid + p * 8;
            *(uint4*)&Bs[nt*128 + bk*8 + bq*4] = tf4(rb[p]);
        }
        __syncthreads();
        if (k0 + 16 < Kc) PREFETCH(k0 + 16)
        #pragma unroll
        for (int c = 0; c < 2; c++) {
            unsigned a[4][4];
            const unsigned* s0 = &As[(c*2)*520];
            const unsigned* s1 = &As[(c*2+1)*520];
            #pragma unroll
            for (int mi = 0; mi < 4; mi++) {
                int m0 = (wr*4 + mi) * 16;
                a[mi][0] = s0[(m0+gid)*4 + tig];
                a[mi][1] = s0[(m0+gid+8)*4 + tig];
                a[mi][2] = s1[(m0+gid)*4 + tig];
                a[mi][3] = s1[(m0+gid+8)*4 + tig];
            }
            #pragma unroll
            for (int ni = 0; ni < 8; ni++) {
                int nt = wc*8 + ni;
                unsigned b[2];
                b[0] = Bs[nt*128 + (c*8+tig)*8 + gid];
                b[1] = Bs[nt*128 + (c*8+tig+4)*8 + gid];
                #pragma unroll
                for (int mi = 0; mi < 4; mi++) mma_tf32(acc[mi][ni], a[mi], b);
            }
        }
        __syncthreads();
    }
    #undef PREFETCH
    // epilogue
    #pragma unroll
    for (int mi = 0; mi < 4; mi++) {
        #pragma unroll
        for (int ni = 0; ni < 8; ni++) {
            int row = row0 + (wr*4 + mi)*16 + gid;
            int col = col0 + (wc*8 + ni)*8 + tig*2;
            *(float2*)(C + (size_t)row * Nc + col) =
                make_float2(acc[mi][ni][0], acc[mi][ni][1]);
            *(float2*)(C + (size_t)(row+8) * Nc + col) =
                make_float2(acc[mi][ni][2], acc[mi][ni][3]);
        }
    }
}

__global__ __launch_bounds__(256, 1)
void k_gemm3(const float* __restrict__ B0, const float* __restrict__ B1,
             const float* __restrict__ B2,
             const float* __restrict__ cw0, const float* __restrict__ cw1,
             const float* __restrict__ cw2,
             float* __restrict__ C0, float* __restrict__ C1,
             float* __restrict__ C2) {
    const float* Bm = (blockIdx.z == 0) ? B0 : ((blockIdx.z == 1) ? B1 : B2);
    const float* cw = (blockIdx.z == 0) ? cw0 : ((blockIdx.z == 1) ? cw1 : cw2);
    float* C = (blockIdx.z == 0) ? C0 : ((blockIdx.z == 1) ? C1 : C2);
    gemm_tc<true>(nullptr, Bm, C, DIi, DIMM, cw);
}

__global__ __launch_bounds__(256, 1)
void k_gemm1(const float* __restrict__ A, const float* __restrict__ Bm,
             float* __restrict__ C, int Nc, int Kc) {
    gemm_tc<false>(A, Bm, C, Nc, Kc, nullptr);
}

// ---------------- 3. gate projections, split-K, 64-row tiles --------------
__global__ void k_gates2(const float* __restrict__ lw, const float* __restrict__ dw,
                         const float* __restrict__ mw) {
    __shared__ float As[64][20];
    __shared__ float Ws[16][24];
    int tid = threadIdx.x;
    int hh = tid & 7, ty = tid >> 3;
    int row0 = blockIdx.x * 64;
    int kbase = blockIdx.y * 128;
    float acc[2][3] = {};
    for (int k0 = kbase; k0 < kbase + 128; k0 += 16) {
        {
            int mm = tid >> 2, kq = (tid & 3) * 4;
            float4 v = *(const float4*)(g_xa + (size_t)(row0+mm)*DIMM + k0 + kq);
            As[mm][kq+0]=v.x; As[mm][kq+1]=v.y; As[mm][kq+2]=v.z; As[mm][kq+3]=v.w;
        }
        if (tid < 128) {
            int kk = tid >> 3, h2 = tid & 7;
            Ws[kk][h2]    = lw[(k0+kk)*Hh + h2];
            Ws[kk][8+h2]  = dw[(k0+kk)*Hh + h2];
            Ws[kk][16+h2] = mw[(k0+kk)*Hh + h2];
        }
        __syncthreads();
        #pragma unroll
        for (int kk = 0; kk < 16; kk++) {
            float a0 = As[ty*2][kk], a1 = As[ty*2+1][kk];
            float w0 = Ws[kk][hh], w1 = Ws[kk][8+hh], w2 = Ws[kk][16+hh];
            acc[0][0] += a0*w0; acc[0][1] += a0*w1; acc[0][2] += a0*w2;
            acc[1][0] += a1*w0; acc[1][1] += a1*w1; acc[1][2] += a1*w2;
        }
        __syncthreads();
    }
    #pragma unroll
    for (int i = 0; i < 2; i++) {
        int row = row0 + ty*2 + i;
        atomicAdd(&g_ga[row*24 + hh],      acc[i][0]);
        atomicAdd(&g_ga[row*24 + 8 + hh],  acc[i][1]);
        atomicAdd(&g_ga[row*24 + 16 + hh], acc[i][2]);
    }
}

// ---------------- 4. per-head RMSNorm of q, k ----------------
__global__ void k_mhnorm(const float* __restrict__ gq, const float* __restrict__ gk) {
    int row = blockIdx.x;
    int h = threadIdx.x >> 5, l = threadIdx.x & 31;
    size_t off = (size_t)row * DIi + h * DHh;
    {
        float a0 = g_qp[off + l], a1 = g_qp[off + l + 32];
        float ss = a0*a0 + a1*a1;
        #pragma unroll
        for (int o = 16; o > 0; o >>= 1) ss += __shfl_xor_sync(0xffffffffu, ss, o);
        float inv = 1.f / fmaxf(sqrtf(ss) * 0.125f, 1e-8f);
        g_qp[off + l]      = a0 * inv * gq[h*DHh + l];
        g_qp[off + l + 32] = a1 * inv * gq[h*DHh + l + 32];
    }
    {
        float a0 = g_kp[off + l], a1 = g_kp[off + l + 32];
        float ss = a0*a0 + a1*a1;
        #pragma unroll
        for (int o = 16; o > 0; o >>= 1) ss += __shfl_xor_sync(0xffffffffu, ss, o);
        float inv = 1.f / fmaxf(sqrtf(ss) * 0.125f, 1e-8f);
        g_kp[off + l]      = a0 * inv * gk[h*DHh + l];
        g_kp[off + l + 32] = a1 * inv * gk[h*DHh + l + 32];
    }
}

// ---------------- 5. scan: 8 col-blocks per (b,h), 8-step groups ----------
__global__ void k_scan(const float* __restrict__ lb, const float* __restrict__ db,
                       const float* __restrict__ mb) {
    int bh = blockIdx.x >> 3, jb = blockIdx.x & 7;
    int b = bh >> 3, h = bh & 7;
    int j0g = jb * JB;
    int tid = threadIdx.x;           // 256
    int r = tid >> 2, c = tid & 3;
    __shared__ float sq[2][TG][JB], sk[2][TG][JB], sv[2][TG][64], sg[2][TG][4];
    float Z0=0.f, Z1=0.f, S0=0.f, S1=0.f;
    const size_t base = (size_t)b * Nn * DIi + h * DHh;

    int vstep = tid >> 6, vrow = tid & 63;
    bool qrole = (tid < 64), krole = (tid >= 64 && tid < 128);
    bool grole = (tid >= 128 && tid < 152);
    int qkstep = (tid & 63) >> 3, qkj = tid & 7;
    int gidx = tid - 128;
    int gstep = gidx / 3, ggi = gidx - gstep * 3;
    float gbias = 0.f;
    if (grole) {
        const float* bsrc = (ggi == 0) ? lb : ((ggi == 1) ? db : mb);
        gbias = bsrc[h];
    }

    float pv0, pv1, pq = 0.f, pk = 0.f, pg = 0.f;
    pv0 = g_vp[base + (size_t)vstep * DIi + vrow];
    pv1 = g_vp[base + (size_t)(vstep+4) * DIi + vrow];
    if (qrole) pq = g_qp[base + (size_t)qkstep * DIi + j0g + qkj];
    if (krole) pk = g_kp[base + (size_t)qkstep * DIi + j0g + qkj];
    if (grole) {
        float raw = g_ga[(size_t)(b*Nn + gstep)*24 + ggi*8 + h] + gbias;
        pg = 1.f / (1.f + __expf(-raw));
    }
    sv[0][vstep][vrow] = pv0;
    sv[0][vstep+4][vrow] = pv1;
    if (qrole) sq[0][qkstep][qkj] = pq;
    if (krole) sk[0][qkstep][qkj] = pk;
    if (grole) sg[0][gstep][ggi] = pg;
    __syncthreads();

    int cur = 0;
    for (int g0 = 0; g0 < Nn / TG; g0++) {
        int t0 = g0 * TG;
        bool hasnext = (g0 + 1 < Nn / TG);
        if (hasnext) {
            int tn = t0 + TG;
            pv0 = g_vp[base + (size_t)(tn+vstep) * DIi + vrow];
            pv1 = g_vp[base + (size_t)(tn+vstep+4) * DIi + vrow];
            if (qrole) pq = g_qp[base + (size_t)(tn+qkstep) * DIi + j0g + qkj];
            if (krole) pk = g_kp[base + (size_t)(tn+qkstep) * DIi + j0g + qkj];
            if (grole) {
                float raw = g_ga[(size_t)(b*Nn + tn + gstep)*24 + ggi*8 + h] + gbias;
                pg = 1.f / (1.f + __expf(-raw));
            }
        }
        #pragma unroll
        for (int s = 0; s < TG; s++) {
            float q0 = sq[cur][s][c*2], q1 = sq[cur][s][c*2+1];
            float p = S0*q0 + S1*q1;
            p += __shfl_xor_sync(0xffffffffu, p, 1);
            p += __shfl_xor_sync(0xffffffffu, p, 2);
            if (c == 0) atomicAdd(&g_y[base + (size_t)(t0+s)*DIi + r], p);
            float vr  = sv[cur][s][r];
            float k0v = sk[cur][s][c*2], k1v = sk[cur][s][c*2+1];
            float lrt = sg[cur][s][0], det = sg[cur][s][1], mot = sg[cur][s][2];
            Z0 = mot*Z0 - vr*k0v;  S0 = det*S0 - lrt*Z0;
            Z1 = mot*Z1 - vr*k1v;  S1 = det*S1 - lrt*Z1;
        }
        __syncthreads();
        if (hasnext) {
            int nxt = cur ^ 1;
            sv[nxt][vstep][vrow] = pv0;
            sv[nxt][vstep+4][vrow] = pv1;
            if (qrole) sq[nxt][qkstep][qkj] = pq;
            if (krole) sk[nxt][qkstep][qkj] = pk;
            if (grole) sg[nxt][gstep][ggi] = pg;
        }
        __syncthreads();
        cur ^= 1;
    }
}

// ---------------- launch ----------------
extern "C" void kernel_launch(void* const* d_in, const int* in_sizes, int n_in,
                              void* d_out, int out_size) {
    const float* x      = (const float*)d_in[0];
    const float* w_rms  = (const float*)d_in[1];
    const float* wq     = (const float*)d_in[2];
    const float* wk     = (const float*)d_in[3];
    const float* wv     = (const float*)d_in[4];
    const float* wo     = (const float*)d_in[5];
    const float* conv_q = (const float*)d_in[6];
    const float* conv_k = (const float*)d_in[7];
    const float* conv_v = (const float*)d_in[8];
    const float* gamma_q= (const float*)d_in[9];
    const float* gamma_k= (const float*)d_in[10];
    const float* lr_w   = (const float*)d_in[11];
    const float* lr_b   = (const float*)d_in[12];
    const float* decay_w= (const float*)d_in[13];
    const float* decay_b= (const float*)d_in[14];
    const float* mom_w  = (const float*)d_in[15];
    const float* mom_b  = (const float*)d_in[16];
    float* out = (float*)d_out;

    float *p_qp, *p_kp, *p_vp, *p_y, *p_ga;
    cudaGetSymbolAddress((void**)&p_qp, g_qp);
    cudaGetSymbolAddress((void**)&p_kp, g_kp);
    cudaGetSymbolAddress((void**)&p_vp, g_vp);
    cudaGetSymbolAddress((void**)&p_y,  g_y);
    cudaGetSymbolAddress((void**)&p_ga, g_ga);

    cudaMemsetAsync(p_ga, 0, (size_t)BN * 24 * sizeof(float));
    cudaMemsetAsync(p_y,  0, (size_t)BN * DIi * sizeof(float));

    k_rmsnorm<<<BN, 256>>>(x, w_rms);
    dim3 gqkv(DIi/256, BN/128, 3);
    k_gemm3<<<gqkv, 256>>>(wq, wk, wv, conv_q, conv_k, conv_v, p_qp, p_kp, p_vp);
    dim3 ggate(BN/64, 8);
    k_gates2<<<ggate, 256>>>(lr_w, decay_w, mom_w);
    k_mhnorm<<<BN, 256>>>(gamma_q, gamma_k);
    k_scan<<<Bb*Hh*8, 256>>>(lr_b, decay_b, mom_b);
    dim3 gout(DIMM/256, BN/128);
    k_gemm1<<<gout, 256>>>(p_y, wo, out, DIMM, DIi);
}